// round 1
// baseline (speedup 1.0000x reference)
#include <cuda_runtime.h>
#include <cuda_bf16.h>
#include <math.h>

#define NN 100000
#define NE 20000
#define NP 3200000
#define D  512

// ---------------- scratch (device globals; no allocation) ----------------
__device__ float4 g_m[NN];        // gelu(x @ Wmsg^T)          [N,4]
__device__ float4 g_u[NN];        // x @ Wupd^T + b            [N,4]
__device__ float  g_esum[NE * 4]; // edge accumulators
__device__ float  g_ecnt[NE];
__device__ float4 g_ef[NE];       // edge means
__device__ float  g_nsum[NN * 4]; // node accumulators (pass 2)
__device__ float  g_ncnt[NN];

__device__ __forceinline__ float gelu_exact(float v) {
    return 0.5f * v * (1.0f + erff(v * 0.70710678118654752f));
}

// ---------------- kernel 0: zero the accumulators ----------------
__global__ void k_init() {
    int i = blockIdx.x * blockDim.x + threadIdx.x;
    int stride = gridDim.x * blockDim.x;
    for (int j = i; j < NE * 4; j += stride) g_esum[j] = 0.0f;
    for (int j = i; j < NE;     j += stride) g_ecnt[j] = 0.0f;
    for (int j = i; j < NN * 4; j += stride) g_nsum[j] = 0.0f;
    for (int j = i; j < NN;     j += stride) g_ncnt[j] = 0.0f;
}

// ---------------- kernel 1: fused dual GEMV + GELU ----------------
// Each warp computes 4 rows; 8 output features (Wmsg rows 0-3, Wupd rows 4-7).
// W lives in shared (8 x 512 fp32 = 16KB). x read once, coalesced float4.
__global__ __launch_bounds__(256) void k_linear(
    const float4* __restrict__ x4,      // [N, 128] float4
    const float4* __restrict__ wmsg4,   // [4, 128]
    const float4* __restrict__ wupd4,   // [4, 128]
    const float*  __restrict__ b_upd)   // [4]
{
    __shared__ float4 sW[8 * 128];
    __shared__ float  sB[4];

    int t = threadIdx.x;
    for (int i = t; i < 4 * 128; i += 256) sW[i] = wmsg4[i];
    for (int i = t; i < 4 * 128; i += 256) sW[4 * 128 + i] = wupd4[i];
    if (t < 4) sB[t] = b_upd[t];
    __syncthreads();

    int warp = t >> 5;
    int lane = t & 31;
    int row0 = (blockIdx.x * 8 + warp) * 4;   // N = 100000 = 3125 blocks * 32 rows
    if (row0 >= NN) return;

    float acc[4][8];
    #pragma unroll
    for (int r = 0; r < 4; r++)
        #pragma unroll
        for (int k = 0; k < 8; k++) acc[r][k] = 0.0f;

    #pragma unroll
    for (int i = 0; i < 4; i++) {
        int c = i * 32 + lane;                // float4 column index 0..127
        float4 wv[8];
        #pragma unroll
        for (int k = 0; k < 8; k++) wv[k] = sW[k * 128 + c];
        #pragma unroll
        for (int r = 0; r < 4; r++) {
            float4 xv = x4[(size_t)(row0 + r) * 128 + c];
            #pragma unroll
            for (int k = 0; k < 8; k++) {
                acc[r][k] += xv.x * wv[k].x + xv.y * wv[k].y
                           + xv.z * wv[k].z + xv.w * wv[k].w;
            }
        }
    }

    // butterfly reduce all 32 partial sums across the warp
    #pragma unroll
    for (int r = 0; r < 4; r++)
        #pragma unroll
        for (int k = 0; k < 8; k++)
            #pragma unroll
            for (int off = 16; off > 0; off >>= 1)
                acc[r][k] += __shfl_xor_sync(0xFFFFFFFFu, acc[r][k], off);

    if (lane < 4) {
        int row = row0 + lane;
        float4 mv;
        mv.x = gelu_exact(acc[lane][0]);
        mv.y = gelu_exact(acc[lane][1]);
        mv.z = gelu_exact(acc[lane][2]);
        mv.w = gelu_exact(acc[lane][3]);
        g_m[row] = mv;
        float4 uv;
        uv.x = acc[lane][4] + sB[0];
        uv.y = acc[lane][5] + sB[1];
        uv.z = acc[lane][6] + sB[2];
        uv.w = acc[lane][7] + sB[3];
        g_u[row] = uv;
    }
}

// ---------------- kernel 2: pair scatter #1 (node msgs -> edge sums) ----------------
__global__ __launch_bounds__(256) void k_scatter_edges(
    const int* __restrict__ pair_node,
    const int* __restrict__ pair_edge)
{
    int p = blockIdx.x * blockDim.x + threadIdx.x;
    if (p >= NP) return;
    int n = pair_node[p];
    int e = pair_edge[p];
    float4 mv = g_m[n];
    atomicAdd(&g_esum[e * 4 + 0], mv.x);
    atomicAdd(&g_esum[e * 4 + 1], mv.y);
    atomicAdd(&g_esum[e * 4 + 2], mv.z);
    atomicAdd(&g_esum[e * 4 + 3], mv.w);
    atomicAdd(&g_ecnt[e], 1.0f);
}

// ---------------- kernel 3: edge mean ----------------
__global__ void k_edge_mean() {
    int e = blockIdx.x * blockDim.x + threadIdx.x;
    if (e >= NE) return;
    float inv = 1.0f / fmaxf(g_ecnt[e], 1.0f);
    float4 v;
    v.x = g_esum[e * 4 + 0] * inv;
    v.y = g_esum[e * 4 + 1] * inv;
    v.z = g_esum[e * 4 + 2] * inv;
    v.w = g_esum[e * 4 + 3] * inv;
    g_ef[e] = v;
}

// ---------------- kernel 4: pair scatter #2 (edge means -> node sums) ----------------
__global__ __launch_bounds__(256) void k_scatter_nodes(
    const int* __restrict__ pair_node,
    const int* __restrict__ pair_edge)
{
    int p = blockIdx.x * blockDim.x + threadIdx.x;
    if (p >= NP) return;
    int n = pair_node[p];
    int e = pair_edge[p];
    float4 ev = g_ef[e];
    atomicAdd(&g_nsum[n * 4 + 0], ev.x);
    atomicAdd(&g_nsum[n * 4 + 1], ev.y);
    atomicAdd(&g_nsum[n * 4 + 2], ev.z);
    atomicAdd(&g_nsum[n * 4 + 3], ev.w);
    atomicAdd(&g_ncnt[n], 1.0f);
}

// ---------------- kernel 5: update + log_softmax ----------------
__global__ void k_final(float4* __restrict__ out4) {
    int i = blockIdx.x * blockDim.x + threadIdx.x;
    if (i >= NN) return;
    float4 u = g_u[i];
    float inv = 1.0f / fmaxf(g_ncnt[i], 1.0f);
    const float4 s = reinterpret_cast<const float4*>(g_nsum)[i];
    float h0 = gelu_exact(u.x + s.x * inv);
    float h1 = gelu_exact(u.y + s.y * inv);
    float h2 = gelu_exact(u.z + s.z * inv);
    float h3 = gelu_exact(u.w + s.w * inv);
    float mx = fmaxf(fmaxf(h0, h1), fmaxf(h2, h3));
    float lse = mx + logf(expf(h0 - mx) + expf(h1 - mx)
                        + expf(h2 - mx) + expf(h3 - mx));
    out4[i] = make_float4(h0 - lse, h1 - lse, h2 - lse, h3 - lse);
}

// ---------------- launch ----------------
extern "C" void kernel_launch(void* const* d_in, const int* in_sizes, int n_in,
                              void* d_out, int out_size) {
    const float* x         = (const float*)d_in[0];
    const int*   pair_node = (const int*)d_in[1];
    const int*   pair_edge = (const int*)d_in[2];
    const float* W_msg     = (const float*)d_in[3];
    const float* W_upd     = (const float*)d_in[4];
    const float* b_upd     = (const float*)d_in[5];
    float4* out4 = (float4*)d_out;

    k_init<<<400, 256>>>();

    k_linear<<<NN / 32, 256>>>((const float4*)x,
                               (const float4*)W_msg,
                               (const float4*)W_upd,
                               b_upd);

    k_scatter_edges<<<(NP + 255) / 256, 256>>>(pair_node, pair_edge);

    k_edge_mean<<<(NE + 255) / 256, 256>>>();

    k_scatter_nodes<<<(NP + 255) / 256, 256>>>(pair_node, pair_edge);

    k_final<<<(NN + 255) / 256, 256>>>(out4);
}

// round 2
// speedup vs baseline: 1.4799x; 1.4799x over previous
#include <cuda_runtime.h>
#include <cuda_bf16.h>
#include <math.h>

#define NN 100000
#define NE 20000
#define NP 3200000
#define D  512

// ---------------- scratch (device globals; no allocation) ----------------
__device__ float4 g_m[NN];        // gelu(x @ Wmsg^T)          [N,4]
__device__ float4 g_u[NN];        // x @ Wupd^T + b            [N,4]
__device__ float4 g_esum[NE];     // edge accumulators (vector atomics)
__device__ float  g_ecnt[NE];
__device__ float4 g_ef[NE];       // edge means
__device__ float4 g_nsum[NN];     // node accumulators (pass 2)
__device__ float  g_ncnt[NN];

__device__ __forceinline__ float gelu_exact(float v) {
    return 0.5f * v * (1.0f + erff(v * 0.70710678118654752f));
}

// ---------------- kernel 0: zero the accumulators ----------------
__global__ void k_init() {
    int i = blockIdx.x * blockDim.x + threadIdx.x;
    int stride = gridDim.x * blockDim.x;
    const float4 z4 = make_float4(0.f, 0.f, 0.f, 0.f);
    for (int j = i; j < NE; j += stride) { g_esum[j] = z4; g_ecnt[j] = 0.0f; }
    for (int j = i; j < NN; j += stride) { g_nsum[j] = z4; g_ncnt[j] = 0.0f; }
}

// ---------------- kernel 1: fused dual GEMV + GELU ----------------
// Each warp computes 4 rows; 8 output features (Wmsg rows 0-3, Wupd rows 4-7).
// W lives in shared (8 x 512 fp32 = 16KB). x read once, coalesced float4.
__global__ __launch_bounds__(256) void k_linear(
    const float4* __restrict__ x4,      // [N, 128] float4
    const float4* __restrict__ wmsg4,   // [4, 128]
    const float4* __restrict__ wupd4,   // [4, 128]
    const float*  __restrict__ b_upd)   // [4]
{
    __shared__ float4 sW[8 * 128];
    __shared__ float  sB[4];

    int t = threadIdx.x;
    for (int i = t; i < 4 * 128; i += 256) sW[i] = wmsg4[i];
    for (int i = t; i < 4 * 128; i += 256) sW[4 * 128 + i] = wupd4[i];
    if (t < 4) sB[t] = b_upd[t];
    __syncthreads();

    int warp = t >> 5;
    int lane = t & 31;
    int row0 = (blockIdx.x * 8 + warp) * 4;   // N = 100000 = 3125 blocks * 32 rows
    if (row0 >= NN) return;

    float acc[4][8];
    #pragma unroll
    for (int r = 0; r < 4; r++)
        #pragma unroll
        for (int k = 0; k < 8; k++) acc[r][k] = 0.0f;

    #pragma unroll
    for (int i = 0; i < 4; i++) {
        int c = i * 32 + lane;                // float4 column index 0..127
        float4 wv[8];
        #pragma unroll
        for (int k = 0; k < 8; k++) wv[k] = sW[k * 128 + c];
        #pragma unroll
        for (int r = 0; r < 4; r++) {
            float4 xv = x4[(size_t)(row0 + r) * 128 + c];
            #pragma unroll
            for (int k = 0; k < 8; k++) {
                acc[r][k] += xv.x * wv[k].x + xv.y * wv[k].y
                           + xv.z * wv[k].z + xv.w * wv[k].w;
            }
        }
    }

    // butterfly reduce all 32 partial sums across the warp
    #pragma unroll
    for (int r = 0; r < 4; r++)
        #pragma unroll
        for (int k = 0; k < 8; k++)
            #pragma unroll
            for (int off = 16; off > 0; off >>= 1)
                acc[r][k] += __shfl_xor_sync(0xFFFFFFFFu, acc[r][k], off);

    if (lane < 4) {
        int row = row0 + lane;
        float4 mv;
        mv.x = gelu_exact(acc[lane][0]);
        mv.y = gelu_exact(acc[lane][1]);
        mv.z = gelu_exact(acc[lane][2]);
        mv.w = gelu_exact(acc[lane][3]);
        g_m[row] = mv;
        float4 uv;
        uv.x = acc[lane][4] + sB[0];
        uv.y = acc[lane][5] + sB[1];
        uv.z = acc[lane][6] + sB[2];
        uv.w = acc[lane][7] + sB[3];
        g_u[row] = uv;
    }
}

// ---------------- kernel 2: pair scatter #1 (node msgs -> edge sums) ----------------
// One float4 vector atomic for the 4-feature sum, plus both count atomics
// (node counts are computed here too, so pass 2 is a single atomic per pair).
__global__ __launch_bounds__(256) void k_scatter_edges(
    const int* __restrict__ pair_node,
    const int* __restrict__ pair_edge)
{
    int p = blockIdx.x * blockDim.x + threadIdx.x;
    if (p >= NP) return;
    int n = __ldg(&pair_node[p]);
    int e = __ldg(&pair_edge[p]);
    float4 mv = g_m[n];
    atomicAdd(&g_esum[e], mv);          // RED.128
    atomicAdd(&g_ecnt[e], 1.0f);
    atomicAdd(&g_ncnt[n], 1.0f);
}

// ---------------- kernel 3: edge mean ----------------
__global__ void k_edge_mean() {
    int e = blockIdx.x * blockDim.x + threadIdx.x;
    if (e >= NE) return;
    float inv = 1.0f / fmaxf(g_ecnt[e], 1.0f);
    float4 s = g_esum[e];
    g_ef[e] = make_float4(s.x * inv, s.y * inv, s.z * inv, s.w * inv);
}

// ---------------- kernel 4: pair scatter #2 (edge means -> node sums) ----------------
__global__ __launch_bounds__(256) void k_scatter_nodes(
    const int* __restrict__ pair_node,
    const int* __restrict__ pair_edge)
{
    int p = blockIdx.x * blockDim.x + threadIdx.x;
    if (p >= NP) return;
    int n = __ldg(&pair_node[p]);
    int e = __ldg(&pair_edge[p]);
    float4 ev = g_ef[e];
    atomicAdd(&g_nsum[n], ev);          // RED.128 (only atomic in this pass)
}

// ---------------- kernel 5: update + log_softmax ----------------
__global__ void k_final(float4* __restrict__ out4) {
    int i = blockIdx.x * blockDim.x + threadIdx.x;
    if (i >= NN) return;
    float4 u = g_u[i];
    float inv = 1.0f / fmaxf(g_ncnt[i], 1.0f);
    float4 s = g_nsum[i];
    float h0 = gelu_exact(u.x + s.x * inv);
    float h1 = gelu_exact(u.y + s.y * inv);
    float h2 = gelu_exact(u.z + s.z * inv);
    float h3 = gelu_exact(u.w + s.w * inv);
    float mx = fmaxf(fmaxf(h0, h1), fmaxf(h2, h3));
    float lse = mx + logf(expf(h0 - mx) + expf(h1 - mx)
                        + expf(h2 - mx) + expf(h3 - mx));
    out4[i] = make_float4(h0 - lse, h1 - lse, h2 - lse, h3 - lse);
}

// ---------------- launch ----------------
extern "C" void kernel_launch(void* const* d_in, const int* in_sizes, int n_in,
                              void* d_out, int out_size) {
    const float* x         = (const float*)d_in[0];
    const int*   pair_node = (const int*)d_in[1];
    const int*   pair_edge = (const int*)d_in[2];
    const float* W_msg     = (const float*)d_in[3];
    const float* W_upd     = (const float*)d_in[4];
    const float* b_upd     = (const float*)d_in[5];
    float4* out4 = (float4*)d_out;

    k_init<<<240, 256>>>();

    k_linear<<<NN / 32, 256>>>((const float4*)x,
                               (const float4*)W_msg,
                               (const float4*)W_upd,
                               b_upd);

    k_scatter_edges<<<(NP + 255) / 256, 256>>>(pair_node, pair_edge);

    k_edge_mean<<<(NE + 255) / 256, 256>>>();

    k_scatter_nodes<<<(NP + 255) / 256, 256>>>(pair_node, pair_edge);

    k_final<<<(NN + 255) / 256, 256>>>(out4);
}

// round 3
// speedup vs baseline: 1.7451x; 1.1792x over previous
#include <cuda_runtime.h>
#include <cuda_bf16.h>
#include <math.h>

#define NN 100000
#define NE 20000
#define NP 3200000
#define D  512
#define NREP 4                    // edge accumulator replicas (contention 160 -> 40)

// ---------------- scratch (device globals; no allocation) ----------------
__device__ float4 g_m[NN];            // gelu(x @ Wmsg^T)         [N,4]
__device__ float4 g_u[NN];            // x @ Wupd^T + b           [N,4]
__device__ float4 g_esum[NREP * NE];  // replicated edge accumulators
__device__ float  g_ecnt[NREP * NE];
__device__ float4 g_ef[NE];           // edge means
__device__ float4 g_nsum[NN];         // node accumulators (pass 2)
__device__ float  g_ncnt[NN];

__device__ __forceinline__ float gelu_exact(float v) {
    return 0.5f * v * (1.0f + erff(v * 0.70710678118654752f));
}

// ---------------- packed f32x2 helpers (sm_100a) ----------------
__device__ __forceinline__ unsigned long long pk2(float a, float b) {
    unsigned long long r;
    asm("mov.b64 %0, {%1, %2};" : "=l"(r) : "f"(a), "f"(b));
    return r;
}
__device__ __forceinline__ void fma2(unsigned long long& d,
                                     unsigned long long a,
                                     unsigned long long b) {
    asm("fma.rn.f32x2 %0, %1, %2, %0;" : "+l"(d) : "l"(a), "l"(b));
}
__device__ __forceinline__ float upk_sum(unsigned long long v) {
    float x, y;
    asm("mov.b64 {%0, %1}, %2;" : "=f"(x), "=f"(y) : "l"(v));
    return x + y;
}

// ---------------- kernel 0: zero the accumulators ----------------
__global__ void k_init() {
    int i = blockIdx.x * blockDim.x + threadIdx.x;
    int stride = gridDim.x * blockDim.x;
    const float4 z4 = make_float4(0.f, 0.f, 0.f, 0.f);
    for (int j = i; j < NREP * NE; j += stride) { g_esum[j] = z4; g_ecnt[j] = 0.0f; }
    for (int j = i; j < NN;        j += stride) { g_nsum[j] = z4; g_ncnt[j] = 0.0f; }
}

// ---------------- kernel 1: fused dual GEMV + GELU (f32x2) ----------------
// Each warp computes 2 rows; 8 output features (Wmsg rows 0-3, Wupd rows 4-7).
// W lives in shared (16KB). x read once, coalesced float4.
__global__ __launch_bounds__(256) void k_linear(
    const float4* __restrict__ x4,      // [N, 128] float4
    const float4* __restrict__ wmsg4,   // [4, 128]
    const float4* __restrict__ wupd4,   // [4, 128]
    const float*  __restrict__ b_upd)   // [4]
{
    __shared__ float4 sW[8 * 128];
    __shared__ float  sB[4];

    int t = threadIdx.x;
    for (int i = t; i < 4 * 128; i += 256) sW[i] = wmsg4[i];
    for (int i = t; i < 4 * 128; i += 256) sW[4 * 128 + i] = wupd4[i];
    if (t < 4) sB[t] = b_upd[t];
    __syncthreads();

    int warp = t >> 5;
    int lane = t & 31;
    int row0 = (blockIdx.x * 8 + warp) * 2;   // N = 100000 = 6250 blocks * 16 rows

    unsigned long long acc2[2][8];
    #pragma unroll
    for (int r = 0; r < 2; r++)
        #pragma unroll
        for (int k = 0; k < 8; k++) acc2[r][k] = 0ull;

    #pragma unroll
    for (int i = 0; i < 4; i++) {
        int c = i * 32 + lane;                // float4 column index 0..127
        unsigned long long wlo[8], whi[8];
        #pragma unroll
        for (int k = 0; k < 8; k++) {
            float4 wv = sW[k * 128 + c];
            wlo[k] = pk2(wv.x, wv.y);
            whi[k] = pk2(wv.z, wv.w);
        }
        #pragma unroll
        for (int r = 0; r < 2; r++) {
            float4 xv = x4[(size_t)(row0 + r) * 128 + c];
            unsigned long long xlo = pk2(xv.x, xv.y);
            unsigned long long xhi = pk2(xv.z, xv.w);
            #pragma unroll
            for (int k = 0; k < 8; k++) {
                fma2(acc2[r][k], xlo, wlo[k]);
                fma2(acc2[r][k], xhi, whi[k]);
            }
        }
    }

    // collapse packed halves, butterfly reduce across the warp
    float acc[2][8];
    #pragma unroll
    for (int r = 0; r < 2; r++)
        #pragma unroll
        for (int k = 0; k < 8; k++) {
            float s = upk_sum(acc2[r][k]);
            #pragma unroll
            for (int off = 16; off > 0; off >>= 1)
                s += __shfl_xor_sync(0xFFFFFFFFu, s, off);
            acc[r][k] = s;
        }

    if (lane < 2) {
        int row = row0 + lane;
        float4 mv;
        mv.x = gelu_exact(acc[lane][0]);
        mv.y = gelu_exact(acc[lane][1]);
        mv.z = gelu_exact(acc[lane][2]);
        mv.w = gelu_exact(acc[lane][3]);
        g_m[row] = mv;
        float4 uv;
        uv.x = acc[lane][4] + sB[0];
        uv.y = acc[lane][5] + sB[1];
        uv.z = acc[lane][6] + sB[2];
        uv.w = acc[lane][7] + sB[3];
        g_u[row] = uv;
    }
}

// ---------------- kernel 2: pair scatter #1 (node msgs -> edge sums) ----------------
// 4 pairs per thread (int4 index loads). Edge accumulators are 4-way
// replicated to cut per-address RED serialization. Node counts also done here.
__global__ __launch_bounds__(256) void k_scatter_edges(
    const int4* __restrict__ pn4,
    const int4* __restrict__ pe4)
{
    int t = blockIdx.x * blockDim.x + threadIdx.x;
    if (t >= NP / 4) return;
    int4 n4 = __ldg(&pn4[t]);
    int4 e4 = __ldg(&pe4[t]);
    int rep = (threadIdx.x & 3) * NE;

    #pragma unroll
    for (int j = 0; j < 4; j++) {
        int n = (j == 0) ? n4.x : (j == 1) ? n4.y : (j == 2) ? n4.z : n4.w;
        int e = (j == 0) ? e4.x : (j == 1) ? e4.y : (j == 2) ? e4.z : e4.w;
        float4 mv = g_m[n];
        atomicAdd(&g_esum[rep + e], mv);      // RED.128
        atomicAdd(&g_ecnt[rep + e], 1.0f);
        atomicAdd(&g_ncnt[n], 1.0f);
    }
}

// ---------------- kernel 3: edge mean (sum replicas) ----------------
__global__ void k_edge_mean() {
    int e = blockIdx.x * blockDim.x + threadIdx.x;
    if (e >= NE) return;
    float4 s = make_float4(0.f, 0.f, 0.f, 0.f);
    float cnt = 0.0f;
    #pragma unroll
    for (int r = 0; r < NREP; r++) {
        float4 v = g_esum[r * NE + e];
        s.x += v.x; s.y += v.y; s.z += v.z; s.w += v.w;
        cnt += g_ecnt[r * NE + e];
    }
    float inv = 1.0f / fmaxf(cnt, 1.0f);
    g_ef[e] = make_float4(s.x * inv, s.y * inv, s.z * inv, s.w * inv);
}

// ---------------- kernel 4: pair scatter #2 (edge means -> node sums) ----------------
__global__ __launch_bounds__(256) void k_scatter_nodes(
    const int4* __restrict__ pn4,
    const int4* __restrict__ pe4)
{
    int t = blockIdx.x * blockDim.x + threadIdx.x;
    if (t >= NP / 4) return;
    int4 n4 = __ldg(&pn4[t]);
    int4 e4 = __ldg(&pe4[t]);

    #pragma unroll
    for (int j = 0; j < 4; j++) {
        int n = (j == 0) ? n4.x : (j == 1) ? n4.y : (j == 2) ? n4.z : n4.w;
        int e = (j == 0) ? e4.x : (j == 1) ? e4.y : (j == 2) ? e4.z : e4.w;
        float4 ev = g_ef[e];
        atomicAdd(&g_nsum[n], ev);            // RED.128 (only atomic here)
    }
}

// ---------------- kernel 5: update + log_softmax ----------------
__global__ void k_final(float4* __restrict__ out4) {
    int i = blockIdx.x * blockDim.x + threadIdx.x;
    if (i >= NN) return;
    float4 u = g_u[i];
    float inv = 1.0f / fmaxf(g_ncnt[i], 1.0f);
    float4 s = g_nsum[i];
    float h0 = gelu_exact(u.x + s.x * inv);
    float h1 = gelu_exact(u.y + s.y * inv);
    float h2 = gelu_exact(u.z + s.z * inv);
    float h3 = gelu_exact(u.w + s.w * inv);
    float mx = fmaxf(fmaxf(h0, h1), fmaxf(h2, h3));
    float lse = mx + logf(expf(h0 - mx) + expf(h1 - mx)
                        + expf(h2 - mx) + expf(h3 - mx));
    out4[i] = make_float4(h0 - lse, h1 - lse, h2 - lse, h3 - lse);
}

// ---------------- launch ----------------
extern "C" void kernel_launch(void* const* d_in, const int* in_sizes, int n_in,
                              void* d_out, int out_size) {
    const float* x         = (const float*)d_in[0];
    const int*   pair_node = (const int*)d_in[1];
    const int*   pair_edge = (const int*)d_in[2];
    const float* W_msg     = (const float*)d_in[3];
    const float* W_upd     = (const float*)d_in[4];
    const float* b_upd     = (const float*)d_in[5];
    float4* out4 = (float4*)d_out;

    k_init<<<512, 256>>>();

    k_linear<<<NN / 16, 256>>>((const float4*)x,
                               (const float4*)W_msg,
                               (const float4*)W_upd,
                               b_upd);

    k_scatter_edges<<<(NP / 4 + 255) / 256, 256>>>((const int4*)pair_node,
                                                   (const int4*)pair_edge);

    k_edge_mean<<<(NE + 255) / 256, 256>>>();

    k_scatter_nodes<<<(NP / 4 + 255) / 256, 256>>>((const int4*)pair_node,
                                                   (const int4*)pair_edge);

    k_final<<<(NN + 255) / 256, 256>>>(out4);
}